// round 13
// baseline (speedup 1.0000x reference)
#include <cuda_runtime.h>
#include <math.h>

#define NPTS    8192
#define KNN     16
#define KL      17               // 16 + self slot (self edge contributes 0)
#define G       32
#define G3      (G*G*G)
#define BMAXF   6.0f
#define QTPB    64
#define WPB     (QTPB/32)        // 2 warps per block; warp = 32 queries
#define IDXMASK 8191
#define FULLM   0xFFFFFFFFu

__device__ double   g_acc;
__device__ unsigned g_done;
__device__ int    g_cnt[4*G3];
__device__ int    g_cstart[4*(G3+1)];
__device__ int    g_cofs[4*G3];
__device__ int    g_cellid[4*NPTS];
__device__ float4 g_sref4[4*NPTS];    // counting-sorted: (x,y,z,|p|^2/2)
__device__ float4 g_spred4[4*NPTS];

__device__ __forceinline__ int cell_of(float x, float y, float z) {
    const float inv_h = (float)G / (2.0f * BMAXF);
    int cx = (int)((x + BMAXF) * inv_h);
    int cy = (int)((y + BMAXF) * inv_h);
    int cz = (int)((z + BMAXF) * inv_h);
    cx = min(G-1, max(0, cx)); cy = min(G-1, max(0, cy)); cz = min(G-1, max(0, cz));
    return (cz * G + cy) * G + cx;
}

__global__ void k_zero(int ncells_total) {
    int i = blockIdx.x * blockDim.x + threadIdx.x;
    if (i == 0) { g_acc = 0.0; g_done = 0u; }
    if (i < ncells_total) g_cnt[i] = 0;
}

__global__ void k_hist(const float* __restrict__ pref, int total) {
    int i = blockIdx.x * blockDim.x + threadIdx.x;
    if (i >= total) return;
    int b = i / NPTS;
    int c = cell_of(pref[3*i], pref[3*i+1], pref[3*i+2]);
    g_cellid[i] = c;
    atomicAdd(&g_cnt[b * G3 + c], 1);
}

__global__ __launch_bounds__(1024) void k_scan() {   // grid = B blocks
    const int CH = G3 / 1024;                        // 32
    __shared__ int ps[1024];
    int b = blockIdx.x, t = threadIdx.x;
    int base = b * G3;
    int loc[CH];
    int s = 0;
#pragma unroll
    for (int u = 0; u < CH; u++) { loc[u] = s; s += g_cnt[base + t*CH + u]; }
    ps[t] = s;
    __syncthreads();
    for (int off = 1; off < 1024; off <<= 1) {
        int v = (t >= off) ? ps[t - off] : 0;
        __syncthreads();
        ps[t] += v;
        __syncthreads();
    }
    int excl = (t == 0) ? 0 : ps[t-1];
#pragma unroll
    for (int u = 0; u < CH; u++) {
        int c = t*CH + u;
        int st = excl + loc[u];
        g_cstart[b*(G3+1) + c] = st;
        g_cofs[base + c] = st;
    }
    if (t == 1023) g_cstart[b*(G3+1) + G3] = ps[1023];
}

__global__ void k_scatter(const float* __restrict__ pref,
                          const float* __restrict__ ppred, int total) {
    int i = blockIdx.x * blockDim.x + threadIdx.x;
    if (i >= total) return;
    int b = i / NPTS;
    int c = g_cellid[i];
    int pos = b * NPTS + atomicAdd(&g_cofs[b * G3 + c], 1);
    float x = pref[3*i], y = pref[3*i+1], z = pref[3*i+2];
    g_sref4[pos]  = make_float4(x, y, z, 0.5f*(x*x + y*y + z*z));
    g_spred4[pos] = make_float4(ppred[3*i], ppred[3*i+1], ppred[3*i+2], 0.0f);
}

// ------ warp = 32 coherent queries; shared box-shell candidate stream ------
__global__ __launch_bounds__(QTPB)
void k_query(float* __restrict__ out, float inv_total, int nblk_total) {
    __shared__ float4 sbuf[WPB][32];
    __shared__ int    spid[WPB][32];
    __shared__ float  wsum[WPB];

    const int lane  = threadIdx.x & 31;
    const int w     = threadIdx.x >> 5;
    const int qwarp = blockIdx.x * WPB + w;        // 0..1023
    const int b     = qwarp >> 8;                  // 256 warps per batch
    const int i     = (qwarp & 255) * 32 + lane;   // batch-local sorted index
    const int pbase = b * NPTS;
    const int cbase = b * (G3 + 1);

    const float4 q = g_sref4[pbase + i];
    const float xi = q.x, yi = q.y, zi = q.z, hq = q.w;
    const float inv_h = (float)G / (2.0f * BMAXF);
    const float h     = (2.0f * BMAXF) / (float)G;
    const int cx = min(G-1, max(0, (int)((xi + BMAXF) * inv_h)));
    const int cy = min(G-1, max(0, (int)((yi + BMAXF) * inv_h)));
    const int cz = min(G-1, max(0, (int)((zi + BMAXF) * inv_h)));

    // warp cell bounding box
    int bx0 = cx, bx1 = cx, by0 = cy, by1 = cy, bz0 = cz, bz1 = cz;
#pragma unroll
    for (int o = 16; o > 0; o >>= 1) {
        bx0 = min(bx0, __shfl_xor_sync(FULLM, bx0, o));
        bx1 = max(bx1, __shfl_xor_sync(FULLM, bx1, o));
        by0 = min(by0, __shfl_xor_sync(FULLM, by0, o));
        by1 = max(by1, __shfl_xor_sync(FULLM, by1, o));
        bz0 = min(bz0, __shfl_xor_sync(FULLM, bz0, o));
        bz1 = max(bz1, __shfl_xor_sync(FULLM, bz1, o));
    }

    const float INF = __int_as_float(0x7F800000);
    // per-lane sorted top-17 of (score-with-packed-index)
    float val[KL];
#pragma unroll
    for (int k = 0; k < KL; k++) val[k] = __int_as_float(0x7F000000);
    float cmax = __int_as_float(0x7F000000);

    for (int rho = 0; ; rho++) {
        const int Ey = (by1 - by0 + 1) + 2 * rho;
        const int Ez = (bz1 - bz0 + 1) + 2 * rho;
        const int n_rows = (rho == 0) ? Ey * Ez
                         : 2*Ey + 2*(Ez-2) + 2*(Ez-2)*(Ey-2);

        for (int rbase = 0; rbase < n_rows; rbase += 32) {
            const int r = rbase + lane;
            int p0 = 0, cnt = 0;
            if (r < n_rows) {
                int y, z, xa, xb;
                if (rho == 0) {
                    y = by0 + (r % Ey);
                    z = bz0 + (r / Ey);
                    xa = bx0; xb = bx1;
                } else if (r < 2 * Ey) {
                    z = (r < Ey) ? (bz0 - rho) : (bz1 + rho);
                    y = by0 - rho + ((r < Ey) ? r : (r - Ey));
                    xa = bx0 - rho; xb = bx1 + rho;
                } else {
                    int r2 = r - 2 * Ey;
                    int nB = 2 * (Ez - 2);
                    if (r2 < nB) {
                        int half = Ez - 2;
                        z = bz0 - rho + 1 + ((r2 < half) ? r2 : (r2 - half));
                        y = (r2 < half) ? (by0 - rho) : (by1 + rho);
                        xa = bx0 - rho; xb = bx1 + rho;
                    } else {
                        int r3 = r2 - nB;
                        int pair = r3 >> 1;
                        int dy = pair % (Ey - 2), dz = pair / (Ey - 2);
                        y = by0 - rho + 1 + dy;
                        z = bz0 - rho + 1 + dz;
                        int x = (r3 & 1) ? (bx1 + rho) : (bx0 - rho);
                        xa = x; xb = x;
                    }
                }
                xa = max(xa, 0); xb = min(xb, G - 1);
                if (y >= 0 && y < G && z >= 0 && z < G && xa <= xb) {
                    int c0 = (z * G + y) * G + xa;
                    p0 = g_cstart[cbase + c0];
                    cnt = g_cstart[cbase + c0 + (xb - xa) + 1] - p0;
                }
            }
            // exclusive prefix scan of row counts
            int off = cnt;
#pragma unroll
            for (int d = 1; d < 32; d <<= 1) {
                int v = __shfl_up_sync(FULLM, off, d);
                if (lane >= d) off += v;
            }
            const int T = __shfl_sync(FULLM, off, 31);
            off -= cnt;

            auto slot_to_p = [&](int gq) {
                int lo = 0, hi = 31;
#pragma unroll
                for (int it = 0; it < 5; it++) {
                    int mid = (lo + hi + 1) >> 1;
                    int om = __shfl_sync(FULLM, off, mid);
                    if (om <= gq) lo = mid; else hi = mid - 1;
                }
                int offr = __shfl_sync(FULLM, off, lo);
                int p0r  = __shfl_sync(FULLM, p0,  lo);
                return p0r + (gq - offr);
            };

            for (int g0 = 0; g0 < T; g0 += 32) {
                const int g = g0 + lane;
                const int gq = min(g, T - 1);
                int pp = slot_to_p(gq);             // all lanes participate
                int pid = (g < T) ? pp : -1;

                __syncwarp();                        // prior reads done
                sbuf[w][lane] = g_sref4[pbase + pp];
                spid[w][lane] = pid;
                __syncwarp();                        // writes visible

                // every lane scores all 32 staged candidates vs its own query
#pragma unroll
                for (int u0 = 0; u0 < 32; u0 += 4) {
                    float s4[4]; int pc[4];
#pragma unroll
                    for (int u = 0; u < 4; u++) {
                        float4 c = sbuf[w][u0 + u];
                        pc[u] = spid[w][u0 + u];
                        float sc = fmaf(-c.x, xi,
                                    fmaf(-c.y, yi,
                                    fmaf(-c.z, zi, c.w + hq)));
                        s4[u] = (pc[u] >= 0) ? sc : INF;
                    }
                    float mn = fminf(fminf(s4[0], s4[1]), fminf(s4[2], s4[3]));
                    if (mn < cmax) {
#pragma unroll
                        for (int u = 0; u < 4; u++) {
                            if (s4[u] < cmax) {
                                float cv = __int_as_float(
                                    (__float_as_int(s4[u]) & ~IDXMASK) | pc[u]);
#pragma unroll
                                for (int k = 0; k < KL; k++) {
                                    float lo = fminf(cv, val[k]);
                                    float hi = fmaxf(cv, val[k]);
                                    val[k] = lo; cv = hi;
                                }
                                cmax = val[KL - 1];
                            }
                        }
                    }
                }
            }
        }

        // per-lane exact stop: distance from query to expanded-box boundary
        float dmin = INF;
        if (bx0 - rho > 0)     dmin = fminf(dmin, xi - ((float)(bx0 - rho) * h - BMAXF));
        if (bx1 + rho < G - 1) dmin = fminf(dmin, ((float)(bx1 + rho + 1) * h - BMAXF) - xi);
        if (by0 - rho > 0)     dmin = fminf(dmin, yi - ((float)(by0 - rho) * h - BMAXF));
        if (by1 + rho < G - 1) dmin = fminf(dmin, ((float)(by1 + rho + 1) * h - BMAXF) - yi);
        if (bz0 - rho > 0)     dmin = fminf(dmin, zi - ((float)(bz0 - rho) * h - BMAXF));
        if (bz1 + rho < G - 1) dmin = fminf(dmin, ((float)(bz1 + rho + 1) * h - BMAXF) - zi);
        bool done = (dmin == INF) || (2.0f * cmax + 1e-4f <= dmin * dmin);
        if (__all_sync(FULLM, done)) break;
    }

    // epilogue: exact edge lengths for this lane's 17 entries (self -> 0)
    float s = 0.0f;
    const float4 qp = g_spred4[pbase + i];
#pragma unroll
    for (int k = 0; k < KL; k++) {
        int j = __float_as_int(val[k]) & IDXMASK;
        float4 rr = g_sref4[pbase + j];
        float4 pp = g_spred4[pbase + j];
        float dx = rr.x - xi, dy = rr.y - yi, dz = rr.z - zi;
        float dr = sqrtf(fmaf(dx, dx, fmaf(dy, dy, dz*dz)));
        float ex = pp.x - qp.x, ey = pp.y - qp.y, ez = pp.z - qp.z;
        float dp = sqrtf(fmaf(ex, ex, fmaf(ey, ey, ez*ez)));
        s += fabsf(dr - dp);
    }

#pragma unroll
    for (int o = 16; o > 0; o >>= 1)
        s += __shfl_down_sync(FULLM, s, o);
    if (lane == 0) wsum[w] = s;
    __syncthreads();

    if (threadIdx.x == 0) {
        float tt = 0.0f;
#pragma unroll
        for (int u = 0; u < WPB; u++) tt += wsum[u];
        atomicAdd(&g_acc, (double)tt);
        __threadfence();
        unsigned old = atomicAdd(&g_done, 1u);
        if (old == (unsigned)(nblk_total - 1)) {
            double total = atomicAdd(&g_acc, 0.0);
            out[0] = (float)total * inv_total;
        }
    }
}

extern "C" void kernel_launch(void* const* d_in, const int* in_sizes, int n_in,
                              void* d_out, int out_size) {
    const float* points_ref = (const float*)d_in[0];
    const float* points     = (const float*)d_in[1];
    float* out = (float*)d_out;

    const int B = in_sizes[0] / (NPTS * 3);               // 4
    const int total_pts = B * NPTS;
    const int ncells = B * G3;
    const float inv_total = 1.0f / (float)(B * NPTS * KNN);
    const int qblocks = total_pts / (WPB * 32);           // 512 blocks

    k_zero<<<(ncells + 255) / 256, 256>>>(ncells);
    k_hist<<<(total_pts + 255) / 256, 256>>>(points_ref, total_pts);
    k_scan<<<B, 1024>>>();
    k_scatter<<<(total_pts + 255) / 256, 256>>>(points_ref, points, total_pts);
    k_query<<<qblocks, QTPB>>>(out, inv_total, qblocks);
}

// round 14
// speedup vs baseline: 2.4671x; 2.4671x over previous
#include <cuda_runtime.h>
#include <math.h>

#define NPTS    8192
#define KNN     16
#define KL      17               // 16 + self slot (self edge contributes 0)
#define G       32
#define G3      (G*G*G)
#define BMAXF   6.0f
#define QTPB    256
#define WPB     (QTPB/32)        // 8 queries (warps) per block
#define FULLM   0xFFFFFFFFu

__device__ double   g_acc;
__device__ unsigned g_done;
__device__ int    g_cnt[4*G3];
__device__ int    g_cstart[4*(G3+1)];
__device__ int    g_cofs[4*G3];
__device__ int    g_cellid[4*NPTS];
__device__ float4 g_sref4[4*NPTS];    // counting-sorted: (x,y,z,|p|^2/2)
__device__ float4 g_spred4[4*NPTS];

__device__ __forceinline__ int cell_of(float x, float y, float z) {
    const float inv_h = (float)G / (2.0f * BMAXF);
    int cx = (int)((x + BMAXF) * inv_h);
    int cy = (int)((y + BMAXF) * inv_h);
    int cz = (int)((z + BMAXF) * inv_h);
    cx = min(G-1, max(0, cx)); cy = min(G-1, max(0, cy)); cz = min(G-1, max(0, cz));
    return (cz * G + cy) * G + cx;
}

__global__ void k_zero(int ncells_total) {
    int i = blockIdx.x * blockDim.x + threadIdx.x;
    if (i == 0) { g_acc = 0.0; g_done = 0u; }
    if (i < ncells_total) g_cnt[i] = 0;
}

__global__ void k_hist(const float* __restrict__ pref, int total) {
    int i = blockIdx.x * blockDim.x + threadIdx.x;
    if (i >= total) return;
    int b = i / NPTS;
    int c = cell_of(pref[3*i], pref[3*i+1], pref[3*i+2]);
    g_cellid[i] = c;
    atomicAdd(&g_cnt[b * G3 + c], 1);
}

__global__ __launch_bounds__(1024) void k_scan() {   // grid = B blocks
    const int CH = G3 / 1024;                        // 32
    __shared__ int ps[1024];
    int b = blockIdx.x, t = threadIdx.x;
    int base = b * G3;
    int loc[CH];
    int s = 0;
#pragma unroll
    for (int u = 0; u < CH; u++) { loc[u] = s; s += g_cnt[base + t*CH + u]; }
    ps[t] = s;
    __syncthreads();
    for (int off = 1; off < 1024; off <<= 1) {
        int v = (t >= off) ? ps[t - off] : 0;
        __syncthreads();
        ps[t] += v;
        __syncthreads();
    }
    int excl = (t == 0) ? 0 : ps[t-1];
#pragma unroll
    for (int u = 0; u < CH; u++) {
        int c = t*CH + u;
        int st = excl + loc[u];
        g_cstart[b*(G3+1) + c] = st;
        g_cofs[base + c] = st;
    }
    if (t == 1023) g_cstart[b*(G3+1) + G3] = ps[1023];
}

__global__ void k_scatter(const float* __restrict__ pref,
                          const float* __restrict__ ppred, int total) {
    int i = blockIdx.x * blockDim.x + threadIdx.x;
    if (i >= total) return;
    int b = i / NPTS;
    int c = g_cellid[i];
    int pos = b * NPTS + atomicAdd(&g_cofs[b * G3 + c], 1);
    float x = pref[3*i], y = pref[3*i+1], z = pref[3*i+2];
    g_sref4[pos]  = make_float4(x, y, z, 0.5f*(x*x + y*y + z*z));
    g_spred4[pos] = make_float4(ppred[3*i], ppred[3*i+1], ppred[3*i+2], 0.0f);
}

// ------- one warp per query, flattened ring scan + row-AABB pruning -------
__global__ __launch_bounds__(QTPB)
void k_query(float* __restrict__ out, float inv_total, int nblk_total) {
    __shared__ float wsum[WPB];
    const int lane = threadIdx.x & 31;
    const int w    = threadIdx.x >> 5;
    const int qw   = blockIdx.x * WPB + w;
    const int b    = qw >> 13;
    const int i    = qw & (NPTS - 1);          // index into sorted array
    const int pbase = b * NPTS;
    const int cbase = b * (G3 + 1);

    const float4 q = g_sref4[pbase + i];
    const float xi = q.x, yi = q.y, zi = q.z, hq = q.w;
    const float inv_h = (float)G / (2.0f * BMAXF);
    const float h     = (2.0f * BMAXF) / (float)G;
    const int cx = min(G-1, max(0, (int)((xi + BMAXF) * inv_h)));
    const int cy = min(G-1, max(0, (int)((yi + BMAXF) * inv_h)));
    const int cz = min(G-1, max(0, (int)((zi + BMAXF) * inv_h)));

    const float INF = __int_as_float(0x7F800000);
    float myval = INF;      // lane k holds k-th smallest (score, idx)
    int   myidx = i;
    float cmax  = INF;

    auto insert1 = [&](float v, int id) {        // v already < cmax, broadcast
        float pv = __shfl_up_sync(FULLM, myval, 1);
        int   pi = __shfl_up_sync(FULLM, myidx, 1);
        if (lane == 0) pv = -INF;
        if (v <= pv)        { myval = pv; myidx = pi; }
        else if (v < myval) { myval = v;  myidx = id; }
        cmax = __shfl_sync(FULLM, myval, KL - 1);
    };

    auto process = [&](float sc, int p) {
        unsigned m = __ballot_sync(FULLM, sc < cmax);
        if (!m) return;
        if (__popc(m) >= 10) {
            // bitonic sort of chunk, then merge with resident sorted-32 list
            float sv = sc; int si = p;
#pragma unroll
            for (int k = 2; k <= 32; k <<= 1) {
#pragma unroll
                for (int j = k >> 1; j > 0; j >>= 1) {
                    float ov = __shfl_xor_sync(FULLM, sv, j);
                    int   oi = __shfl_xor_sync(FULLM, si, j);
                    bool keep_min = ((lane & j) == 0) == ((lane & k) == 0);
                    bool take = keep_min ? (ov < sv) : (ov > sv);
                    if (take) { sv = ov; si = oi; }
                }
            }
            float rv = __shfl_sync(FULLM, sv, 31 - lane);
            int   ri = __shfl_sync(FULLM, si, 31 - lane);
            if (rv < myval) { myval = rv; myidx = ri; }
#pragma unroll
            for (int j = 16; j > 0; j >>= 1) {
                float ov = __shfl_xor_sync(FULLM, myval, j);
                int   oi = __shfl_xor_sync(FULLM, myidx, j);
                bool keep_min = ((lane & j) == 0);
                bool take = keep_min ? (ov < myval) : (ov > myval);
                if (take) { myval = ov; myidx = oi; }
            }
            cmax = __shfl_sync(FULLM, myval, KL - 1);
        } else {
            while (m) {
                int src = __ffs(m) - 1;
                m &= m - 1;
                float v = __shfl_sync(FULLM, sc, src);
                int  id = __shfl_sync(FULLM, p,  src);
                if (v < cmax) insert1(v, id);
            }
        }
    };

    for (int rho = 0; ; rho++) {
        const int S = 2*rho + 1;
        const int sm2 = S - 2;
        const int n_rows = (rho == 0) ? 1 : 8*rho + 2*sm2*sm2;

        for (int rbase = 0; rbase < n_rows; rbase += 32) {
            const int r = rbase + lane;
            int p0 = 0, cnt = 0;
            if (r < n_rows) {
                int y, z, xa, xb;
                if (rho == 0) { y = cy; z = cz; xa = cx; xb = cx; }
                else if (r < S)        { z = cz - rho; y = cy - rho + r;            xa = cx-rho; xb = cx+rho; }
                else if (r < 2*S)      { z = cz + rho; y = cy - rho + (r - S);      xa = cx-rho; xb = cx+rho; }
                else if (r < 2*S+sm2)  { z = cz - rho + 1 + (r - 2*S); y = cy - rho; xa = cx-rho; xb = cx+rho; }
                else if (r < 2*S+2*sm2){ z = cz - rho + 1 + (r - 2*S - sm2); y = cy + rho; xa = cx-rho; xb = cx+rho; }
                else {
                    int idx2 = r - 8*rho;
                    int pair = idx2 >> 1;
                    int dyi = pair % sm2, dzi = pair / sm2;
                    y = cy - rho + 1 + dyi;
                    z = cz - rho + 1 + dzi;
                    int x = (idx2 & 1) ? cx + rho : cx - rho;
                    xa = x; xb = x;
                }
                xa = max(xa, 0); xb = min(xb, G-1);
                if (y >= 0 && y < G && z >= 0 && z < G && xa <= xb) {
                    // --- row AABB pruning: min d^2 from query to row box ---
                    float ylo = (float)y  * h - BMAXF;
                    float zlo = (float)z  * h - BMAXF;
                    float xlo = (float)xa * h - BMAXF;
                    float xhi = (float)(xb + 1) * h - BMAXF;
                    float dyF = fmaxf(0.0f, fmaxf(ylo - yi, yi - (ylo + h)));
                    float dzF = fmaxf(0.0f, fmaxf(zlo - zi, zi - (zlo + h)));
                    float dxF = fmaxf(0.0f, fmaxf(xlo - xi, xi - xhi));
                    float d2m = fmaf(dxF, dxF, fmaf(dyF, dyF, dzF * dzF));
                    if (d2m <= 2.0f * cmax + 1e-3f) {
                        int c0 = (z*G + y)*G + xa;
                        p0 = g_cstart[cbase + c0];
                        cnt = g_cstart[cbase + c0 + (xb - xa) + 1] - p0;
                    }
                }
            }
            int off = cnt;
#pragma unroll
            for (int d = 1; d < 32; d <<= 1) {
                int v = __shfl_up_sync(FULLM, off, d);
                if (lane >= d) off += v;
            }
            const int T = __shfl_sync(FULLM, off, 31);
            off -= cnt;

            // map flattened slot -> point index via warp binary search
            for (int g0 = 0; g0 < T; g0 += 32) {
                const int g = g0 + lane;
                const int gq = min(g, T - 1);
                int lo = 0, hi = 31;
#pragma unroll
                for (int it = 0; it < 5; it++) {
                    int mid = (lo + hi + 1) >> 1;
                    int om = __shfl_sync(FULLM, off, mid);
                    if (om <= gq) lo = mid; else hi = mid - 1;
                }
                int offr = __shfl_sync(FULLM, off, lo);
                int p0r  = __shfl_sync(FULLM, p0,  lo);
                int p    = p0r + (gq - offr);

                float sc = INF;
                if (g < T) {
                    float4 c = g_sref4[pbase + p];
                    sc = fmaf(-c.x, xi, fmaf(-c.y, yi, fmaf(-c.z, zi, c.w + hq)));
                }
                process(sc, p);
            }
        }

        // exact stop: distance from query to scanned-box boundary
        float dmin = INF;
        if (cx - rho > 0)     dmin = fminf(dmin, xi - ((float)(cx - rho) * h - BMAXF));
        if (cx + rho < G - 1) dmin = fminf(dmin, ((float)(cx + rho + 1) * h - BMAXF) - xi);
        if (cy - rho > 0)     dmin = fminf(dmin, yi - ((float)(cy - rho) * h - BMAXF));
        if (cy + rho < G - 1) dmin = fminf(dmin, ((float)(cy + rho + 1) * h - BMAXF) - yi);
        if (cz - rho > 0)     dmin = fminf(dmin, zi - ((float)(cz - rho) * h - BMAXF));
        if (cz + rho < G - 1) dmin = fminf(dmin, ((float)(cz + rho + 1) * h - BMAXF) - zi);
        if (dmin == INF) break;
        if (2.0f * cmax + 1e-4f <= dmin * dmin) break;
    }

    // epilogue: lane k computes its edge exactly; self entry -> |0-0| = 0
    float s = 0.0f;
    const float4 qp = g_spred4[pbase + i];
    if (lane < KL) {
        int j = myidx;
        float4 rr = g_sref4[pbase + j];
        float4 pp = g_spred4[pbase + j];
        float dx = rr.x - xi, dy = rr.y - yi, dz = rr.z - zi;
        float dr = sqrtf(fmaf(dx, dx, fmaf(dy, dy, dz*dz)));
        float ex = pp.x - qp.x, ey = pp.y - qp.y, ez = pp.z - qp.z;
        float dp = sqrtf(fmaf(ex, ex, fmaf(ey, ey, ez*ez)));
        s = fabsf(dr - dp);
    }
#pragma unroll
    for (int o = 16; o > 0; o >>= 1)
        s += __shfl_down_sync(FULLM, s, o);
    if (lane == 0) wsum[w] = s;
    __syncthreads();

    if (threadIdx.x == 0) {
        float tt = 0.0f;
#pragma unroll
        for (int u = 0; u < WPB; u++) tt += wsum[u];
        atomicAdd(&g_acc, (double)tt);
        __threadfence();
        unsigned old = atomicAdd(&g_done, 1u);
        if (old == (unsigned)(nblk_total - 1)) {
            double total = atomicAdd(&g_acc, 0.0);
            out[0] = (float)total * inv_total;
        }
    }
}

extern "C" void kernel_launch(void* const* d_in, const int* in_sizes, int n_in,
                              void* d_out, int out_size) {
    const float* points_ref = (const float*)d_in[0];
    const float* points     = (const float*)d_in[1];
    float* out = (float*)d_out;

    const int B = in_sizes[0] / (NPTS * 3);               // 4
    const int total_pts = B * NPTS;
    const int ncells = B * G3;
    const float inv_total = 1.0f / (float)(B * NPTS * KNN);
    const int qblocks = total_pts / WPB;                  // 4096

    k_zero<<<(ncells + 255) / 256, 256>>>(ncells);
    k_hist<<<(total_pts + 255) / 256, 256>>>(points_ref, total_pts);
    k_scan<<<B, 1024>>>();
    k_scatter<<<(total_pts + 255) / 256, 256>>>(points_ref, points, total_pts);
    k_query<<<qblocks, QTPB>>>(out, inv_total, qblocks);
}